// round 6
// baseline (speedup 1.0000x reference)
#include <cuda_runtime.h>
#include <cstdint>
#include <math.h>

// ---------------------------------------------------------------------------
// Problem constants
// ---------------------------------------------------------------------------
#define C_TOT   2048
#define HW2     196
#define O_REAL  48
#define MAXB    64
#define M_TILE  64
#define MTILES  196            // 12544 / 64
#define KSPLIT  2
#define K_PER   (C_TOT / KSPLIT)   // 1024
#define KC      128            // k per chunk
#define NCH     (K_PER / KC)   // 8 chunks per CTA
#define NSTEP   (K_PER / 32)   // 32 k32 steps per CTA

// W int8 image: per chunk (16 total), 48 rows x 72 words (32 h + 32 l + 8 pad)
#define ROWW    72
#define CHUNKW  (48 * ROWW)            // 3456 words
#define CHUNK_BYTES (CHUNKW * 4)       // 13824
#define CP_UNITS (CHUNK_BYTES / 16)    // 864

// Scratch
__device__ float    g_part[(size_t)KSPLIT * MAXB * O_REAL * HW2];   // 4.8 MB
__device__ uint32_t g_wimg[(size_t)16 * CHUNKW];                    // 221 KB
__device__ float    g_csum[(size_t)MAXB * 8 * HW2];
__device__ float    g_t2[(size_t)MAXB * 8 * HW2];
__device__ float    g_t1s[(size_t)MAXB * 8];
__device__ float    g_gmp[(size_t)MAXB * 32];

// ---------------------------------------------------------------------------
// helpers
// ---------------------------------------------------------------------------
__device__ __forceinline__ void imma16832(int* c, const uint32_t* a,
                                          uint32_t b0, uint32_t b1) {
    asm volatile(
        "mma.sync.aligned.m16n8k32.row.col.s32.s8.s8.s32 "
        "{%0,%1,%2,%3}, {%4,%5,%6,%7}, {%8,%9}, {%0,%1,%2,%3};"
        : "+r"(c[0]), "+r"(c[1]), "+r"(c[2]), "+r"(c[3])
        : "r"(a[0]), "r"(a[1]), "r"(a[2]), "r"(a[3]), "r"(b0), "r"(b1));
}
// pack 4 ints (each in [-128,127]) into s8x4, byte0 = i0
__device__ __forceinline__ uint32_t pack4(int i0, int i1, int i2, int i3) {
    uint32_t t, r;
    asm("cvt.pack.sat.s8.s32.b32 %0, %1, %2, %3;" : "=r"(t) : "r"(i3), "r"(i2), "r"(0));
    asm("cvt.pack.sat.s8.s32.b32 %0, %1, %2, %3;" : "=r"(r) : "r"(i1), "r"(i0), "r"(t));
    return r;
}
// round-to-nearest fixed point via FMA magic (|v*scale| < 2^21)
__device__ __forceinline__ int fx_rn(float v, float scale) {
    float f = fmaf(v, scale, 12582912.f);      // 2^23 + 2^22
    return __float_as_int(f) - 0x4B400000;
}
__device__ __forceinline__ void split_hl(int X, int& h, int& l) {
    h = (X + 64) >> 7;
    l = X - (h << 7);
}
__device__ __forceinline__ uint32_t smem_u32addr(const void* p) {
    uint32_t a;
    asm("{ .reg .u64 t; cvta.to.shared.u64 t, %1; cvt.u32.u64 %0, t; }" : "=r"(a) : "l"(p));
    return a;
}
__device__ __forceinline__ void cp_async16(uint32_t saddr, const void* gaddr) {
    asm volatile("cp.async.cg.shared.global [%0], [%1], 16;" :: "r"(saddr), "l"(gaddr));
}

// ---------------------------------------------------------------------------
// Prep: W -> int8 h/l image. One thread per output h-word (24576 threads).
// Word hw in [0,32): s = hw>>3, r = hw&7, half = r&1, cq = r>>1,
// k_local = s*32 + half*16 + cq*4 (+0..3). h at [hw], l at [32+hw].
// ---------------------------------------------------------------------------
__global__ void __launch_bounds__(256) wsl_prep_kernel(
    const float* __restrict__ down_w,
    const float* __restrict__ fc_w)
{
    int idx = blockIdx.x * 256 + threadIdx.x;
    if (idx >= 16 * 48 * 32) return;
    int ci  = idx / 1536;
    int rem = idx - ci * 1536;
    int n   = rem >> 5;
    int hw  = rem & 31;
    int s = hw >> 3, r = hw & 7;
    int k_local = s * 32 + (r & 1) * 16 + (r >> 1) * 4;

    const float* wr;
    if (n < 32)      wr = down_w + (size_t)n * C_TOT;
    else if (n < 40) wr = fc_w + (size_t)(n - 32) * (2 * C_TOT);
    else             wr = fc_w + (size_t)(n - 40) * (2 * C_TOT) + C_TOT;

    float4 w = *reinterpret_cast<const float4*>(wr + ci * KC + k_local);
    int h0, l0, h1, l1, h2, l2, h3, l3;
    split_hl(fx_rn(w.x, 131072.f), h0, l0);
    split_hl(fx_rn(w.y, 131072.f), h1, l1);
    split_hl(fx_rn(w.z, 131072.f), h2, l2);
    split_hl(fx_rn(w.w, 131072.f), h3, l3);

    uint32_t* dst = g_wimg + (size_t)(ci * 48 + n) * ROWW;
    dst[hw]      = pack4(h0, h1, h2, h3);
    dst[32 + hw] = pack4(l0, l1, l2, l3);
}

// ---------------------------------------------------------------------------
// Kernel A: int8 2-split GEMM (3 IMMAs per k32). Grid (196, 2), 128 threads.
// out = acc_hh * 2^-14 + acc_cr * 2^-21   (x scale 2^11, w scale 2^17)
// ---------------------------------------------------------------------------
__global__ void __launch_bounds__(128) wsl_mma_kernel(const float* __restrict__ x)
{
    __shared__ __align__(16) uint32_t smem[2 * CHUNKW];   // 27.6 KB
    const uint32_t sbase = smem_u32addr(smem);

    const int tid  = threadIdx.x;
    const int wid  = tid >> 5;
    const int lane = tid & 31;
    const int g    = lane >> 2;
    const int c    = lane & 3;
    const int m_base  = blockIdx.x * M_TILE;
    const int ks      = blockIdx.y;
    const int ks_base = ks * K_PER;
    const int ch0     = ks * NCH;

    const int m0 = m_base + wid * 16 + g;
    const int m1 = m0 + 8;
    const int b0r = m0 / HW2, hw0 = m0 - b0r * HW2;
    const int b1r = m1 / HW2, hw1 = m1 - b1r * HW2;
    const float* pA0 = x + ((size_t)b0r * C_TOT) * HW2 + hw0;
    const float* pA1 = x + ((size_t)b1r * C_TOT) * HW2 + hw1;

    int hh[6][4], cr[6][4];
#pragma unroll
    for (int t = 0; t < 6; t++)
#pragma unroll
        for (int j = 0; j < 4; j++) { hh[t][j] = 0; cr[t][j] = 0; }

    // raw A prefetch (distance 2): [parity][8]: j*4+i -> k = base + 16j + 4c + i
    float r0[2][8], r1[2][8];

    auto ldgA = [&](int sg, int p) {
        const int kb = ks_base + sg * 32 + 4 * c;
#pragma unroll
        for (int j = 0; j < 2; j++) {
            const size_t k = (size_t)(kb + 16 * j);
#pragma unroll
            for (int i = 0; i < 4; i++) {
                r0[p][4 * j + i] = __ldg(pA0 + (k + i) * HW2);
                r1[p][4 * j + i] = __ldg(pA1 + (k + i) * HW2);
            }
        }
    };

    auto issueB = [&](int ch) {
        const char* src = reinterpret_cast<const char*>(g_wimg + (size_t)(ch0 + ch) * CHUNKW);
        const uint32_t dst = sbase + (uint32_t)((ch & 1) * CHUNK_BYTES);
        for (int u = tid; u < CP_UNITS; u += 128)
            cp_async16(dst + u * 16, src + u * 16);
        asm volatile("cp.async.commit_group;" ::: "memory");
    };

    ldgA(0, 0);
    ldgA(1, 1);
    issueB(0);

    for (int ch = 0; ch < NCH; ch++) {
        if (ch + 1 < NCH) {
            issueB(ch + 1);
            asm volatile("cp.async.wait_group 1;" ::: "memory");
        } else {
            asm volatile("cp.async.wait_group 0;" ::: "memory");
        }
        __syncthreads();

        const uint32_t* buf = smem + (ch & 1) * CHUNKW;

#pragma unroll
        for (int kk = 0; kk < 4; kk++) {
            const int sg = ch * 4 + kk;
            const int p  = sg & 1;

            // convert raw A -> int8 frags
            uint32_t ah[4], al[4];
#pragma unroll
            for (int j = 0; j < 2; j++) {
                int h[8], l[8];
#pragma unroll
                for (int i = 0; i < 4; i++) {
                    split_hl(fx_rn(r0[p][4 * j + i], 2048.f), h[i], l[i]);
                    split_hl(fx_rn(r1[p][4 * j + i], 2048.f), h[4 + i], l[4 + i]);
                }
                ah[j * 2]     = pack4(h[0], h[1], h[2], h[3]);   // row m0
                ah[j * 2 + 1] = pack4(h[4], h[5], h[6], h[7]);   // row m1
                al[j * 2]     = pack4(l[0], l[1], l[2], l[3]);
                al[j * 2 + 1] = pack4(l[4], l[5], l[6], l[7]);
            }
            // reorder to mma a-frag: a0=(m0,klo) a1=(m1,klo) a2=(m0,khi) a3=(m1,khi)
            uint32_t afh[4] = { ah[0], ah[1], ah[2], ah[3] };
            uint32_t afl[4] = { al[0], al[1], al[2], al[3] };

            if (sg + 2 < NSTEP) ldgA(sg + 2, p);

#pragma unroll
            for (int t = 0; t < 6; t++) {
                const uint32_t base = (uint32_t)((t * 8 + g) * ROWW + kk * 8 + 2 * c);
                uint2 bh = *reinterpret_cast<const uint2*>(buf + base);
                uint2 bl = *reinterpret_cast<const uint2*>(buf + base + 32);
                imma16832(hh[t], afh, bh.x, bh.y);
                imma16832(cr[t], afh, bl.x, bl.y);
                imma16832(cr[t], afl, bh.x, bh.y);
            }
        }
        __syncthreads();
    }

    // epilogue: combine scales, write partials
    {
        float* base0 = g_part + ((size_t)(ks * MAXB + b0r) * O_REAL) * HW2 + hw0;
        float* base1 = g_part + ((size_t)(ks * MAXB + b1r) * O_REAL) * HW2 + hw1;
        const float s_hh = 6.103515625e-5f;        // 2^-14
        const float s_cr = 4.76837158203125e-7f;   // 2^-21
#pragma unroll
        for (int t = 0; t < 6; t++) {
            const int n0 = t * 8 + 2 * c;
            base0[(size_t)n0 * HW2]       = (float)hh[t][0] * s_hh + (float)cr[t][0] * s_cr;
            base0[(size_t)(n0 + 1) * HW2] = (float)hh[t][1] * s_hh + (float)cr[t][1] * s_cr;
            base1[(size_t)n0 * HW2]       = (float)hh[t][2] * s_hh + (float)cr[t][2] * s_cr;
            base1[(size_t)(n0 + 1) * HW2] = (float)hh[t][3] * s_hh + (float)cr[t][3] * s_cr;
        }
    }
}

// ---------------------------------------------------------------------------
// B1: reduce K-split partials. Grid (64, 6): b x o-group (8 maps each).
//  og<4 : gmp per map, class sums (csum) per hw
//  og==4: t1 row sums
//  og==5: t2 rows (raw)
// ---------------------------------------------------------------------------
__global__ void __launch_bounds__(256) wsl_b1_kernel(const float* __restrict__ down_b)
{
    __shared__ float s[8 * HW2];
    const int b   = blockIdx.x;
    const int og  = blockIdx.y;
    const int tid = threadIdx.x;
    const int w = tid >> 5, lane = tid & 31;

    const float* p0 = g_part + ((size_t)b * O_REAL + og * 8) * HW2;
    const float* p1 = g_part + ((size_t)(MAXB + b) * O_REAL + og * 8) * HW2;

    if (og == 5) {
        float* dst = g_t2 + (size_t)b * 8 * HW2;
        for (int i = tid; i < 8 * HW2; i += 256)
            dst[i] = p0[i] + p1[i];
        return;
    }

    for (int i = tid; i < 8 * HW2; i += 256) {
        float v = p0[i] + p1[i];
        if (og < 4) v += down_b[og * 8 + i / HW2];
        s[i] = v;
    }
    __syncthreads();

    if (og < 4) {
        // per-map max (warp w owns map w)
        float m = -INFINITY;
        for (int h = lane; h < HW2; h += 32) m = fmaxf(m, s[w * HW2 + h]);
#pragma unroll
        for (int off = 16; off > 0; off >>= 1)
            m = fmaxf(m, __shfl_down_sync(0xffffffffu, m, off));
        if (lane == 0) g_gmp[b * 32 + og * 8 + w] = m;
        // class sums
        if (tid < HW2) {
            float c0 = s[tid] + s[HW2 + tid] + s[2 * HW2 + tid] + s[3 * HW2 + tid];
            float c1 = s[4 * HW2 + tid] + s[5 * HW2 + tid] + s[6 * HW2 + tid] + s[7 * HW2 + tid];
            g_csum[((size_t)b * 8 + 2 * og) * HW2 + tid]     = c0;
            g_csum[((size_t)b * 8 + 2 * og + 1) * HW2 + tid] = c1;
        }
    } else {  // og == 4: t1 row sums
        float sm = 0.f;
        for (int h = lane; h < HW2; h += 32) sm += s[w * HW2 + h];
#pragma unroll
        for (int off = 16; off > 0; off >>= 1)
            sm += __shfl_down_sync(0xffffffffu, sm, off);
        if (lane == 0) g_t1s[b * 8 + w] = sm;
    }
}

// ---------------------------------------------------------------------------
// B2: per-batch finish. Grid 64, 256 threads.
// ---------------------------------------------------------------------------
__global__ void __launch_bounds__(256) wsl_b2_kernel(
    const float* __restrict__ fc_b,
    float* __restrict__ out,
    int B)
{
    __shared__ float xout[8];
    __shared__ float t1sh[8];
    __shared__ float red[8 * 8];
    __shared__ float psum[8];

    const int b = blockIdx.x;
    const int tid = threadIdx.x;
    const int w = tid >> 5, lane = tid & 31;

    if (tid < 8) t1sh[tid] = g_t1s[b * 8 + tid];

    if (tid == 0) {
        float sc[8];
        float mx = -INFINITY;
        const float* gm = g_gmp + b * 32;
        for (int j = 0; j < 8; j++) {
            sc[j] = 0.25f * (gm[4 * j] + gm[4 * j + 1] + gm[4 * j + 2] + gm[4 * j + 3]);
            mx = fmaxf(mx, sc[j]);
        }
        float se = 0.f;
        for (int j = 0; j < 8; j++) se += expf(sc[j] - mx);
        float lse = mx + logf(se);
        for (int j = 0; j < 8; j++) {
            float v = sc[j] - lse;
            xout[j] = v;
            out[(size_t)b * 8 + j] = v;
        }
    }
    __syncthreads();

    float v[8];
    if (tid < HW2) {
        const float* cs = g_csum + (size_t)b * 8 * HW2 + tid;
        const float* t2 = g_t2 + (size_t)b * 8 * HW2 + tid;
        float sal = 0.f;
#pragma unroll
        for (int j = 0; j < 8; j++) sal += xout[j] * cs[(size_t)j * HW2];
        sal *= (1.f / 32.f);
#pragma unroll
        for (int j = 0; j < 8; j++) v[j] = sal * t2[(size_t)j * HW2];
    } else {
#pragma unroll
        for (int j = 0; j < 8; j++) v[j] = 0.f;
    }
#pragma unroll
    for (int off = 16; off > 0; off >>= 1) {
#pragma unroll
        for (int j = 0; j < 8; j++)
            v[j] += __shfl_down_sync(0xffffffffu, v[j], off);
    }
    if (lane == 0) {
#pragma unroll
        for (int j = 0; j < 8; j++) red[j * 8 + w] = v[j];
    }
    __syncthreads();
    if (tid < 8) {
        float sm = 0.f;
#pragma unroll
        for (int ww = 0; ww < 8; ww++) sm += red[tid * 8 + ww];
        psum[tid] = sm;
    }
    __syncthreads();

    if (tid == 0) {
        float lg[8];
        float mx = -INFINITY;
        for (int j = 0; j < 8; j++) {
            lg[j] = (t1sh[j] + psum[j]) * (1.f / 196.f) + fc_b[j];
            mx = fmaxf(mx, lg[j]);
        }
        float se = 0.f;
        for (int j = 0; j < 8; j++) se += expf(lg[j] - mx);
        float lse = mx + logf(se);
        for (int j = 0; j < 8; j++)
            out[(size_t)B * 8 + (size_t)b * 8 + j] = lg[j] - lse;
    }
}

// ---------------------------------------------------------------------------
extern "C" void kernel_launch(void* const* d_in, const int* in_sizes, int n_in,
                              void* d_out, int out_size)
{
    const float* x      = (const float*)d_in[0];
    const float* down_w = (const float*)d_in[1];
    const float* down_b = (const float*)d_in[2];
    const float* fc_w   = (const float*)d_in[3];
    const float* fc_b   = (const float*)d_in[4];
    float* out = (float*)d_out;

    int B = in_sizes[0] / (C_TOT * HW2);   // 64

    wsl_prep_kernel<<<96, 256>>>(down_w, fc_w);
    dim3 gridA(MTILES, KSPLIT);
    wsl_mma_kernel<<<gridA, 128>>>(x);
    dim3 gridB1(B, 6);
    wsl_b1_kernel<<<gridB1, 256>>>(down_b);
    wsl_b2_kernel<<<B, 256>>>(fc_b, out, B);
}

// round 7
// speedup vs baseline: 2.4538x; 2.4538x over previous
#include <cuda_runtime.h>
#include <cuda_fp16.h>
#include <cstdint>
#include <math.h>

// ---------------------------------------------------------------------------
// Problem constants
// ---------------------------------------------------------------------------
#define C_TOT   2048
#define HW2     196
#define O_REAL  48
#define MAXB    64
#define M_TILE  64
#define MTILES  196            // 12544 / 64
#define KSPLIT  2
#define K_PER   (C_TOT / KSPLIT)   // 1024
#define KC      128            // k per smem chunk
#define NCH     (K_PER / KC)   // 8 chunks per CTA
#define NSTEP   (K_PER / 32)   // 32 k32 steps per CTA

// W fp16 image: per chunk (16 total), 48 rows x 72 words (64 data + 8 pad)
// Row word layout: k16 step s (8 per chunk) x 8 words:
//   word s*8 + 2c + half : fp16x2( k = 16s + 8*half + 2c, +1 )
#define ROWW    72
#define CHUNKW  (48 * ROWW)            // 3456 words
#define CHUNK_BYTES (CHUNKW * 4)       // 13824
#define CP_UNITS (CHUNK_BYTES / 16)    // 864

// Scratch
__device__ float    g_part[(size_t)KSPLIT * MAXB * O_REAL * HW2];   // 4.8 MB
__device__ uint32_t g_wimg[(size_t)16 * CHUNKW];                    // 221 KB

// ---------------------------------------------------------------------------
// helpers
// ---------------------------------------------------------------------------
__device__ __forceinline__ void hmma16816(float* c, const uint32_t* a,
                                          uint32_t b0, uint32_t b1) {
    asm volatile(
        "mma.sync.aligned.m16n8k16.row.col.f32.f16.f16.f32 "
        "{%0,%1,%2,%3}, {%4,%5,%6,%7}, {%8,%9}, {%0,%1,%2,%3};"
        : "+f"(c[0]), "+f"(c[1]), "+f"(c[2]), "+f"(c[3])
        : "r"(a[0]), "r"(a[1]), "r"(a[2]), "r"(a[3]), "r"(b0), "r"(b1));
}
// pack two fp16 (rn): lo half = e, hi half = o
__device__ __forceinline__ uint32_t h2pack(float e, float o) {
    uint32_t r;
    asm("cvt.rn.f16x2.f32 %0, %1, %2;" : "=r"(r) : "f"(o), "f"(e));
    return r;
}
__device__ __forceinline__ uint32_t smem_u32addr(const void* p) {
    uint32_t a;
    asm("{ .reg .u64 t; cvta.to.shared.u64 t, %1; cvt.u32.u64 %0, t; }" : "=r"(a) : "l"(p));
    return a;
}
__device__ __forceinline__ void cp_async16(uint32_t saddr, const void* gaddr) {
    asm volatile("cp.async.cg.shared.global [%0], [%1], 16;" :: "r"(saddr), "l"(gaddr));
}

// ---------------------------------------------------------------------------
// Prep: W -> fp16 image. One thread per output word (16*48*64 = 49152).
// ---------------------------------------------------------------------------
__global__ void __launch_bounds__(256) wsl_prep_kernel(
    const float* __restrict__ down_w,
    const float* __restrict__ fc_w)
{
    int idx = blockIdx.x * 256 + threadIdx.x;
    if (idx >= 16 * 48 * 64) return;
    int w   = idx & 63;
    int n   = (idx >> 6) % 48;
    int ci  = idx / (48 * 64);
    int s    = w >> 3;
    int r    = w & 7;
    int c    = r >> 1;
    int half = r & 1;
    int k_local = s * 16 + half * 8 + 2 * c;

    const float* wr;
    if (n < 32)      wr = down_w + (size_t)n * C_TOT;
    else if (n < 40) wr = fc_w + (size_t)(n - 32) * (2 * C_TOT);
    else             wr = fc_w + (size_t)(n - 40) * (2 * C_TOT) + C_TOT;

    float2 f = *reinterpret_cast<const float2*>(wr + ci * KC + k_local);
    g_wimg[(size_t)ci * CHUNKW + n * ROWW + w] = h2pack(f.x, f.y);
}

// ---------------------------------------------------------------------------
// Kernel A: fp16 GEMM (1 HMMA per k16 per n-tile). Grid (196, 2), 128 thr.
// ---------------------------------------------------------------------------
__global__ void __launch_bounds__(128) wsl_mma_kernel(const float* __restrict__ x)
{
    __shared__ __align__(16) uint32_t smem[2 * CHUNKW];   // 27.6 KB
    const uint32_t sbase = smem_u32addr(smem);

    const int tid  = threadIdx.x;
    const int wid  = tid >> 5;
    const int lane = tid & 31;
    const int g    = lane >> 2;
    const int c    = lane & 3;
    const int m_base  = blockIdx.x * M_TILE;
    const int ks      = blockIdx.y;
    const int ks_base = ks * K_PER;
    const int ch0     = ks * NCH;

    const int m0 = m_base + wid * 16 + g;
    const int m1 = m0 + 8;
    const int b0r = m0 / HW2, hw0 = m0 - b0r * HW2;
    const int b1r = m1 / HW2, hw1 = m1 - b1r * HW2;
    const float* pA0 = x + ((size_t)b0r * C_TOT) * HW2 + hw0;
    const float* pA1 = x + ((size_t)b1r * C_TOT) * HW2 + hw1;

    float acc[6][4];
#pragma unroll
    for (int t = 0; t < 6; t++)
#pragma unroll
        for (int j = 0; j < 4; j++) acc[t][j] = 0.f;

    // raw A prefetch (distance 2 k32-steps): [parity][4j+i]
    // j = k16 within k32; i: 0 -> k=16j+2c, 1 -> +1, 2 -> k=16j+8+2c, 3 -> +1
    float r0[2][8], r1[2][8];

    auto ldgA = [&](int sg, int p) {
        const int kb = ks_base + sg * 32 + 2 * c;
#pragma unroll
        for (int j = 0; j < 2; j++) {
            const size_t k = (size_t)(kb + 16 * j);
            r0[p][4 * j]     = __ldg(pA0 + k * HW2);
            r0[p][4 * j + 1] = __ldg(pA0 + (k + 1) * HW2);
            r0[p][4 * j + 2] = __ldg(pA0 + (k + 8) * HW2);
            r0[p][4 * j + 3] = __ldg(pA0 + (k + 9) * HW2);
            r1[p][4 * j]     = __ldg(pA1 + k * HW2);
            r1[p][4 * j + 1] = __ldg(pA1 + (k + 1) * HW2);
            r1[p][4 * j + 2] = __ldg(pA1 + (k + 8) * HW2);
            r1[p][4 * j + 3] = __ldg(pA1 + (k + 9) * HW2);
        }
    };

    auto issueB = [&](int ch) {
        const char* src = reinterpret_cast<const char*>(g_wimg + (size_t)(ch0 + ch) * CHUNKW);
        const uint32_t dst = sbase + (uint32_t)((ch & 1) * CHUNK_BYTES);
        for (int u = tid; u < CP_UNITS; u += 128)
            cp_async16(dst + u * 16, src + u * 16);
        asm volatile("cp.async.commit_group;" ::: "memory");
    };

    ldgA(0, 0);
    ldgA(1, 1);
    issueB(0);

    for (int ch = 0; ch < NCH; ch++) {
        if (ch + 1 < NCH) {
            issueB(ch + 1);
            asm volatile("cp.async.wait_group 1;" ::: "memory");
        } else {
            asm volatile("cp.async.wait_group 0;" ::: "memory");
        }
        __syncthreads();

        const uint32_t* buf = smem + (ch & 1) * CHUNKW;

#pragma unroll
        for (int kk = 0; kk < 4; kk++) {
            const int sg = ch * 4 + kk;
            const int p  = sg & 1;

            // convert raw A -> fp16 frags for the two k16 steps of this k32
            uint32_t af[2][4];
#pragma unroll
            for (int j = 0; j < 2; j++) {
                af[j][0] = h2pack(r0[p][4 * j],     r0[p][4 * j + 1]); // m0, k lo
                af[j][1] = h2pack(r1[p][4 * j],     r1[p][4 * j + 1]); // m1, k lo
                af[j][2] = h2pack(r0[p][4 * j + 2], r0[p][4 * j + 3]); // m0, k hi
                af[j][3] = h2pack(r1[p][4 * j + 2], r1[p][4 * j + 3]); // m1, k hi
            }

            if (sg + 2 < NSTEP) ldgA(sg + 2, p);

#pragma unroll
            for (int j = 0; j < 2; j++) {
                const int s = kk * 2 + j;    // k16 step within chunk
#pragma unroll
                for (int t = 0; t < 6; t++) {
                    const uint2 bw = *reinterpret_cast<const uint2*>(
                        buf + (t * 8 + g) * ROWW + s * 8 + 2 * c);
                    hmma16816(acc[t], af[j], bw.x, bw.y);
                }
            }
        }
        __syncthreads();
    }

    // epilogue: write partials
    {
        float* base0 = g_part + ((size_t)(ks * MAXB + b0r) * O_REAL) * HW2 + hw0;
        float* base1 = g_part + ((size_t)(ks * MAXB + b1r) * O_REAL) * HW2 + hw1;
#pragma unroll
        for (int t = 0; t < 6; t++) {
            const int n0 = t * 8 + 2 * c;
            base0[(size_t)n0 * HW2]       = acc[t][0];
            base0[(size_t)(n0 + 1) * HW2] = acc[t][1];
            base1[(size_t)n0 * HW2]       = acc[t][2];
            base1[(size_t)(n0 + 1) * HW2] = acc[t][3];
        }
    }
}

// ---------------------------------------------------------------------------
// Kernel B: per-batch epilogue, 1024 threads.
// ---------------------------------------------------------------------------
__global__ void __launch_bounds__(1024) wsl_final_kernel(
    const float* __restrict__ down_b,
    const float* __restrict__ fc_b,
    float* __restrict__ out,
    int B)
{
    __shared__ float xc[O_REAL * HW2];    // 9408 floats
    __shared__ float gmp[32];
    __shared__ float xout[8];
    __shared__ float red[16 * 32];
    __shared__ float psum[16];

    const int b = blockIdx.x;
    const int tid = threadIdx.x;
    const int w = tid >> 5, lane = tid & 31;

    // Sum the two K-split partials (+ bias), vectorized (196 % 4 == 0).
    {
        const float4* p0 = reinterpret_cast<const float4*>(g_part + ((size_t)b * O_REAL) * HW2);
        const float4* p1 = reinterpret_cast<const float4*>(g_part + ((size_t)(MAXB + b) * O_REAL) * HW2);
        float4* dst = reinterpret_cast<float4*>(xc);
        for (int i = tid; i < (O_REAL * HW2) / 4; i += 1024) {
            float4 a = __ldg(p0 + i);
            float4 c = __ldg(p1 + i);
            int o = i / 49;
            float bias = (o < 32) ? down_b[o] : 0.f;
            dst[i] = make_float4(a.x + c.x + bias, a.y + c.y + bias,
                                 a.z + c.z + bias, a.w + c.w + bias);
        }
    }
    __syncthreads();

    // GMP: warp w (w<32) handles map o=w.
    {
        float m1 = -INFINITY;
        for (int h = lane; h < HW2; h += 32)
            m1 = fmaxf(m1, xc[w * HW2 + h]);
#pragma unroll
        for (int off = 16; off > 0; off >>= 1)
            m1 = fmaxf(m1, __shfl_down_sync(0xffffffffu, m1, off));
        if (lane == 0) gmp[w] = m1;
    }
    __syncthreads();

    if (tid == 0) {
        float sc[8];
        float mx = -INFINITY;
        for (int j = 0; j < 8; j++) {
            sc[j] = 0.25f * (gmp[4 * j] + gmp[4 * j + 1] + gmp[4 * j + 2] + gmp[4 * j + 3]);
            mx = fmaxf(mx, sc[j]);
        }
        float se = 0.f;
        for (int j = 0; j < 8; j++) se += expf(sc[j] - mx);
        float lse = mx + logf(se);
        for (int j = 0; j < 8; j++) {
            float v = sc[j] - lse;
            xout[j] = v;
            out[(size_t)b * 8 + j] = v;
        }
    }
    __syncthreads();

    float v[16];
    if (tid < HW2) {
        float sal = 0.f;
#pragma unroll
        for (int j = 0; j < 8; j++) {
            float cls = xc[(4 * j) * HW2 + tid] + xc[(4 * j + 1) * HW2 + tid] +
                        xc[(4 * j + 2) * HW2 + tid] + xc[(4 * j + 3) * HW2 + tid];
            sal += xout[j] * cls;
        }
        sal *= (1.f / 32.f);
#pragma unroll
        for (int j = 0; j < 8; j++) {
            v[j]     = xc[(32 + j) * HW2 + tid];
            v[8 + j] = sal * xc[(40 + j) * HW2 + tid];
        }
    } else {
#pragma unroll
        for (int k = 0; k < 16; k++) v[k] = 0.f;
    }
#pragma unroll
    for (int off = 16; off > 0; off >>= 1) {
#pragma unroll
        for (int k = 0; k < 16; k++)
            v[k] += __shfl_down_sync(0xffffffffu, v[k], off);
    }
    if (lane == 0) {
#pragma unroll
        for (int k = 0; k < 16; k++) red[k * 32 + w] = v[k];
    }
    __syncthreads();
    if (tid < 16) {
        float s = 0.f;
#pragma unroll
        for (int ww = 0; ww < 32; ww++) s += red[tid * 32 + ww];
        psum[tid] = s;
    }
    __syncthreads();

    if (tid == 0) {
        float lg[8];
        float mx = -INFINITY;
        for (int j = 0; j < 8; j++) {
            lg[j] = (psum[j] + psum[8 + j]) * (1.f / 196.f) + fc_b[j];
            mx = fmaxf(mx, lg[j]);
        }
        float se = 0.f;
        for (int j = 0; j < 8; j++) se += expf(lg[j] - mx);
        float lse = mx + logf(se);
        for (int j = 0; j < 8; j++)
            out[(size_t)B * 8 + (size_t)b * 8 + j] = lg[j] - lse;
    }
}

// ---------------------------------------------------------------------------
extern "C" void kernel_launch(void* const* d_in, const int* in_sizes, int n_in,
                              void* d_out, int out_size)
{
    const float* x      = (const float*)d_in[0];
    const float* down_w = (const float*)d_in[1];
    const float* down_b = (const float*)d_in[2];
    const float* fc_w   = (const float*)d_in[3];
    const float* fc_b   = (const float*)d_in[4];
    float* out = (float*)d_out;

    int B = in_sizes[0] / (C_TOT * HW2);   // 64

    wsl_prep_kernel<<<192, 256>>>(down_w, fc_w);
    dim3 gridA(MTILES, KSPLIT);
    wsl_mma_kernel<<<gridA, 128>>>(x);
    wsl_final_kernel<<<B, 1024>>>(down_b, fc_b, out, B);
}